// round 8
// baseline (speedup 1.0000x reference)
#include <cuda_runtime.h>

// Problem shape (fixed by the dataset's setup_inputs): N=4, C=256, H=128, W=160
#define N_      4
#define C_      256
#define H_      128
#define W_      160
#define HW_     (H_ * W_)          // 20480
#define P_      (N_ * HW_)         // 81920 pixels
#define NBINS   64
#define NSEG    (NBINS + 1)        // 65 segments (bin 64 = invalid/overflow, dropped)
#define A_THREADS 1024
#define A_BLOCKS  (P_ / A_THREADS) // 80
#define B_THREADS 128
#define EPS_NORM  1e-12f

// ---------------- scratch (device globals; no allocation allowed) ----------------
__device__ unsigned char g_idx[P_];                 // per-pixel bin id (0..64)
__device__ int           g_pcount[A_BLOCKS * NSEG]; // per-block partial bin counts
__device__ float         g_sums[2][NBINS * C_];     // per-bin channel sums (S, T)
__device__ float         g_protos[2][NBINS * C_];   // normalized prototypes
__device__ float         g_diff2[NBINS * NBINS];    // per-pair (simS - simT)^2

// ---------------- helpers ----------------
__device__ __forceinline__ float blockReduceSum(float v) {
    __shared__ float sh[32];
    int lane = threadIdx.x & 31;
    int w    = threadIdx.x >> 5;
    #pragma unroll
    for (int o = 16; o; o >>= 1) v += __shfl_down_sync(0xffffffffu, v, o);
    __syncthreads();                 // protect sh from a previous invocation
    if (lane == 0) sh[w] = v;
    __syncthreads();
    int nw = (blockDim.x + 31) >> 5;
    float r = (threadIdx.x < nw) ? sh[threadIdx.x] : 0.0f;
    if (w == 0) {
        #pragma unroll
        for (int o = 16; o; o >>= 1) r += __shfl_down_sync(0xffffffffu, r, o);
    }
    if (threadIdx.x == 0) sh[0] = r;
    __syncthreads();
    r = sh[0];
    __syncthreads();
    return r;
}

// ---------------- kernel A: bin indices + partial counts ----------------
__global__ void __launch_bounds__(A_THREADS) kA_bins(const float* __restrict__ depth) {
    __shared__ int sc[NSEG];
    int tid = threadIdx.x;
    if (tid < NSEG) sc[tid] = 0;
    __syncthreads();

    int p = blockIdx.x * A_THREADS + tid;
    float d = depth[p];
    float f = d * 64.0f;             // (d - 0) / (1/64), exact (power of two)
    int b;
    if (f >= 0.0f && f <= 64.0f) {   // NaN fails both -> invalid
        b = (int)f;                  // truncation toward zero, matches int cast
    } else {
        b = NBINS;                   // invalid -> segment 64 (dropped)
    }
    g_idx[p] = (unsigned char)b;
    atomicAdd(&sc[b], 1);
    __syncthreads();
    if (tid < NSEG) g_pcount[blockIdx.x * NSEG + tid] = sc[tid];
}

// ---------------- kernel B: per-bin channel sums (the heavy one) ----------------
// grid (C_, 2): blockIdx.x = channel, blockIdx.y = tensor (0=S, 1=T).
// Per-thread privatized bins, bin-major layout acc[bin*128 + tid]:
// each lane always hits bank (tid & 31) -> conflict-free RMW, no atomics.
__global__ void __launch_bounds__(B_THREADS) kB_binsum(const float* __restrict__ fS,
                                                       const float* __restrict__ fT) {
    __shared__ float acc[NSEG * B_THREADS];  // 65*128*4 = 33,280 B
    const float* feats = (blockIdx.y == 0) ? fS : fT;
    const int c   = blockIdx.x;
    const int tid = threadIdx.x;

    #pragma unroll
    for (int i = tid; i < NSEG * B_THREADS; i += B_THREADS) acc[i] = 0.0f;
    __syncthreads();

    const int QUADS = HW_ / 4;  // 5120 float4 per (n, c) chunk
    for (int n = 0; n < N_; n++) {
        const float4* __restrict__ src =
            reinterpret_cast<const float4*>(feats) + (size_t)(n * C_ + c) * QUADS;
        const uchar4* __restrict__ bsrc =
            reinterpret_cast<const uchar4*>(g_idx) + (size_t)n * QUADS;

        // 5120 quads / (128 threads * 4-deep batch) = 10 iterations, exact.
        for (int q0 = tid; q0 < QUADS; q0 += B_THREADS * 4) {
            // batch loads first -> MLP 8 per warp, hides DRAM latency
            float4 v0 = src[q0];
            float4 v1 = src[q0 + B_THREADS];
            float4 v2 = src[q0 + 2 * B_THREADS];
            float4 v3 = src[q0 + 3 * B_THREADS];
            uchar4 b0 = bsrc[q0];
            uchar4 b1 = bsrc[q0 + B_THREADS];
            uchar4 b2 = bsrc[q0 + 2 * B_THREADS];
            uchar4 b3 = bsrc[q0 + 3 * B_THREADS];

            acc[b0.x * B_THREADS + tid] += v0.x;
            acc[b0.y * B_THREADS + tid] += v0.y;
            acc[b0.z * B_THREADS + tid] += v0.z;
            acc[b0.w * B_THREADS + tid] += v0.w;
            acc[b1.x * B_THREADS + tid] += v1.x;
            acc[b1.y * B_THREADS + tid] += v1.y;
            acc[b1.z * B_THREADS + tid] += v1.z;
            acc[b1.w * B_THREADS + tid] += v1.w;
            acc[b2.x * B_THREADS + tid] += v2.x;
            acc[b2.y * B_THREADS + tid] += v2.y;
            acc[b2.z * B_THREADS + tid] += v2.z;
            acc[b2.w * B_THREADS + tid] += v2.w;
            acc[b3.x * B_THREADS + tid] += v3.x;
            acc[b3.y * B_THREADS + tid] += v3.y;
            acc[b3.z * B_THREADS + tid] += v3.z;
            acc[b3.w * B_THREADS + tid] += v3.w;
        }
    }
    __syncthreads();

    // Reduce 128 partials per bin; write bins 0..63 only (bin 64 dropped).
    int warp = tid >> 5, lane = tid & 31;
    for (int b = warp; b < NBINS; b += 4) {
        const float* row = &acc[b * B_THREADS];
        float s = row[lane] + row[lane + 32] + row[lane + 64] + row[lane + 96];
        #pragma unroll
        for (int o = 16; o; o >>= 1) s += __shfl_down_sync(0xffffffffu, s, o);
        if (lane == 0) g_sums[blockIdx.y][b * C_ + c] = s;
    }
}

// ---------------- kernel C: counts reduce + mean + L2-normalize ----------------
// grid (NBINS, 2), 256 threads; thread t = channel t.
__global__ void __launch_bounds__(C_) kC_protos() {
    const int bin = blockIdx.x;
    const int ten = blockIdx.y;
    const int tid = threadIdx.x;

    // count for this bin (sum of per-block partials; exact in fp32, <= 81920)
    float cpart = 0.0f;
    for (int k = tid; k < A_BLOCKS; k += C_) cpart += (float)g_pcount[k * NSEG + bin];
    float count = blockReduceSum(cpart);

    float inv = 1.0f / fmaxf(count, 1.0f);
    float m = g_sums[ten][bin * C_ + tid] * inv;

    float ss = blockReduceSum(m * m);
    float scale = 1.0f / fmaxf(sqrtf(ss), EPS_NORM);
    g_protos[ten][bin * C_ + tid] = m * scale;
}

// ---------------- kernel D: per-pair Gram diff^2 ----------------
// grid NBINS*NBINS, 128 threads. Protos (128 KB total) are L2-hot.
__global__ void __launch_bounds__(128) kD_pairs() {
    const int pair = blockIdx.x;
    const int i = pair >> 6;
    const int j = pair & 63;
    const int tid = threadIdx.x;

    const float* pS = g_protos[0];
    const float* pT = g_protos[1];

    float a = pS[i * C_ + tid] * pS[j * C_ + tid] +
              pS[i * C_ + tid + 128] * pS[j * C_ + tid + 128];
    float b = pT[i * C_ + tid] * pT[j * C_ + tid] +
              pT[i * C_ + tid + 128] * pT[j * C_ + tid + 128];

    __shared__ float sha[4], shb[4];
    int lane = tid & 31, w = tid >> 5;
    #pragma unroll
    for (int o = 16; o; o >>= 1) {
        a += __shfl_down_sync(0xffffffffu, a, o);
        b += __shfl_down_sync(0xffffffffu, b, o);
    }
    if (lane == 0) { sha[w] = a; shb[w] = b; }
    __syncthreads();
    if (tid == 0) {
        float A = sha[0] + sha[1] + sha[2] + sha[3];
        float B = shb[0] + shb[1] + shb[2] + shb[3];
        float d = A - B;
        g_diff2[pair] = d * d;
    }
}

// ---------------- kernel E: final mean ----------------
__global__ void __launch_bounds__(1024) kE_final(float* __restrict__ out) {
    int tid = threadIdx.x;
    float v = g_diff2[tid] + g_diff2[tid + 1024] +
              g_diff2[tid + 2048] + g_diff2[tid + 3072];
    float total = blockReduceSum(v);
    if (tid == 0) out[0] = total * (1.0f / (float)(NBINS * NBINS));
}

// ---------------- launch ----------------
extern "C" void kernel_launch(void* const* d_in, const int* in_sizes, int n_in,
                              void* d_out, int out_size) {
    (void)in_sizes; (void)n_in; (void)out_size;
    const float* S     = (const float*)d_in[0];
    const float* T     = (const float*)d_in[1];
    const float* depth = (const float*)d_in[2];
    float* out = (float*)d_out;

    kA_bins<<<A_BLOCKS, A_THREADS>>>(depth);

    dim3 gB(C_, 2);
    kB_binsum<<<gB, B_THREADS>>>(S, T);

    dim3 gC(NBINS, 2);
    kC_protos<<<gC, C_>>>();

    kD_pairs<<<NBINS * NBINS, 128>>>();

    kE_final<<<1, 1024>>>(out);
}

// round 9
// speedup vs baseline: 1.0010x; 1.0010x over previous
#include <cuda_runtime.h>

// Problem shape (fixed by the dataset's setup_inputs): N=4, C=256, H=128, W=160
#define N_      4
#define C_      256
#define H_      128
#define W_      160
#define HW_     (H_ * W_)          // 20480
#define P_      (N_ * HW_)         // 81920 pixels
#define NBINS   64
#define NSEG    (NBINS + 1)        // 65 segments (bin 64 = invalid/overflow, dropped)
#define A_THREADS 1024
#define A_BLOCKS  (P_ / A_THREADS) // 80
#define B_THREADS 128
#define EPS_NORM  1e-12f

// ---------------- scratch (device globals; no allocation allowed) ----------------
__device__ unsigned char g_idx[P_];                 // per-pixel bin id (0..64)
__device__ int           g_pcount[A_BLOCKS * NSEG]; // per-block partial bin counts
__device__ float         g_sums[2][NBINS * C_];     // per-bin channel sums (S, T)
__device__ float         g_protos[2][NBINS * C_];   // normalized prototypes
__device__ float         g_diff2[NBINS * NBINS];    // per-pair (simS - simT)^2

// ---------------- helpers ----------------
__device__ __forceinline__ float blockReduceSum(float v) {
    __shared__ float sh[32];
    int lane = threadIdx.x & 31;
    int w    = threadIdx.x >> 5;
    #pragma unroll
    for (int o = 16; o; o >>= 1) v += __shfl_down_sync(0xffffffffu, v, o);
    __syncthreads();                 // protect sh from a previous invocation
    if (lane == 0) sh[w] = v;
    __syncthreads();
    int nw = (blockDim.x + 31) >> 5;
    float r = (threadIdx.x < nw) ? sh[threadIdx.x] : 0.0f;
    if (w == 0) {
        #pragma unroll
        for (int o = 16; o; o >>= 1) r += __shfl_down_sync(0xffffffffu, r, o);
    }
    if (threadIdx.x == 0) sh[0] = r;
    __syncthreads();
    r = sh[0];
    __syncthreads();
    return r;
}

// ---------------- kernel A: bin indices + partial counts ----------------
__global__ void __launch_bounds__(A_THREADS) kA_bins(const float* __restrict__ depth) {
    __shared__ int sc[NSEG];
    int tid = threadIdx.x;
    if (tid < NSEG) sc[tid] = 0;
    __syncthreads();

    int p = blockIdx.x * A_THREADS + tid;
    float d = depth[p];
    float f = d * 64.0f;             // (d - 0) / (1/64), exact (power of two)
    int b;
    if (f >= 0.0f && f <= 64.0f) {   // NaN fails both -> invalid
        b = (int)f;                  // truncation toward zero, matches int cast
    } else {
        b = NBINS;                   // invalid -> segment 64 (dropped)
    }
    g_idx[p] = (unsigned char)b;
    atomicAdd(&sc[b], 1);
    __syncthreads();
    if (tid < NSEG) g_pcount[blockIdx.x * NSEG + tid] = sc[tid];
}

// ---------------- kernel B: per-bin channel sums (the heavy one) ----------------
// grid (C_, 2): blockIdx.x = channel, blockIdx.y = tensor (0=S, 1=T).
// Per-thread privatized bins, bin-major layout acc[bin*128 + tid]:
// each lane always hits bank (tid & 31) -> conflict-free RMW, no atomics.
__global__ void __launch_bounds__(B_THREADS) kB_binsum(const float* __restrict__ fS,
                                                       const float* __restrict__ fT) {
    __shared__ float acc[NSEG * B_THREADS];  // 65*128*4 = 33,280 B
    const float* feats = (blockIdx.y == 0) ? fS : fT;
    const int c   = blockIdx.x;
    const int tid = threadIdx.x;

    #pragma unroll
    for (int i = tid; i < NSEG * B_THREADS; i += B_THREADS) acc[i] = 0.0f;
    __syncthreads();

    const int QUADS = HW_ / 4;  // 5120 float4 per (n, c) chunk
    for (int n = 0; n < N_; n++) {
        const float4* __restrict__ src =
            reinterpret_cast<const float4*>(feats) + (size_t)(n * C_ + c) * QUADS;
        const uchar4* __restrict__ bsrc =
            reinterpret_cast<const uchar4*>(g_idx) + (size_t)n * QUADS;

        // 5120 quads / (128 threads * 4-deep batch) = 10 iterations, exact.
        for (int q0 = tid; q0 < QUADS; q0 += B_THREADS * 4) {
            // batch loads first -> MLP 8 per warp, hides DRAM latency
            float4 v0 = src[q0];
            float4 v1 = src[q0 + B_THREADS];
            float4 v2 = src[q0 + 2 * B_THREADS];
            float4 v3 = src[q0 + 3 * B_THREADS];
            uchar4 b0 = bsrc[q0];
            uchar4 b1 = bsrc[q0 + B_THREADS];
            uchar4 b2 = bsrc[q0 + 2 * B_THREADS];
            uchar4 b3 = bsrc[q0 + 3 * B_THREADS];

            acc[b0.x * B_THREADS + tid] += v0.x;
            acc[b0.y * B_THREADS + tid] += v0.y;
            acc[b0.z * B_THREADS + tid] += v0.z;
            acc[b0.w * B_THREADS + tid] += v0.w;
            acc[b1.x * B_THREADS + tid] += v1.x;
            acc[b1.y * B_THREADS + tid] += v1.y;
            acc[b1.z * B_THREADS + tid] += v1.z;
            acc[b1.w * B_THREADS + tid] += v1.w;
            acc[b2.x * B_THREADS + tid] += v2.x;
            acc[b2.y * B_THREADS + tid] += v2.y;
            acc[b2.z * B_THREADS + tid] += v2.z;
            acc[b2.w * B_THREADS + tid] += v2.w;
            acc[b3.x * B_THREADS + tid] += v3.x;
            acc[b3.y * B_THREADS + tid] += v3.y;
            acc[b3.z * B_THREADS + tid] += v3.z;
            acc[b3.w * B_THREADS + tid] += v3.w;
        }
    }
    __syncthreads();

    // Reduce 128 partials per bin; write bins 0..63 only (bin 64 dropped).
    int warp = tid >> 5, lane = tid & 31;
    for (int b = warp; b < NBINS; b += 4) {
        const float* row = &acc[b * B_THREADS];
        float s = row[lane] + row[lane + 32] + row[lane + 64] + row[lane + 96];
        #pragma unroll
        for (int o = 16; o; o >>= 1) s += __shfl_down_sync(0xffffffffu, s, o);
        if (lane == 0) g_sums[blockIdx.y][b * C_ + c] = s;
    }
}

// ---------------- kernel C: counts reduce + mean + L2-normalize ----------------
// grid (NBINS, 2), 256 threads; thread t = channel t.
__global__ void __launch_bounds__(C_) kC_protos() {
    const int bin = blockIdx.x;
    const int ten = blockIdx.y;
    const int tid = threadIdx.x;

    // count for this bin (sum of per-block partials; exact in fp32, <= 81920)
    float cpart = 0.0f;
    for (int k = tid; k < A_BLOCKS; k += C_) cpart += (float)g_pcount[k * NSEG + bin];
    float count = blockReduceSum(cpart);

    float inv = 1.0f / fmaxf(count, 1.0f);
    float m = g_sums[ten][bin * C_ + tid] * inv;

    float ss = blockReduceSum(m * m);
    float scale = 1.0f / fmaxf(sqrtf(ss), EPS_NORM);
    g_protos[ten][bin * C_ + tid] = m * scale;
}

// ---------------- kernel D: per-pair Gram diff^2 ----------------
// grid NBINS*NBINS, 128 threads. Protos (128 KB total) are L2-hot.
__global__ void __launch_bounds__(128) kD_pairs() {
    const int pair = blockIdx.x;
    const int i = pair >> 6;
    const int j = pair & 63;
    const int tid = threadIdx.x;

    const float* pS = g_protos[0];
    const float* pT = g_protos[1];

    float a = pS[i * C_ + tid] * pS[j * C_ + tid] +
              pS[i * C_ + tid + 128] * pS[j * C_ + tid + 128];
    float b = pT[i * C_ + tid] * pT[j * C_ + tid] +
              pT[i * C_ + tid + 128] * pT[j * C_ + tid + 128];

    __shared__ float sha[4], shb[4];
    int lane = tid & 31, w = tid >> 5;
    #pragma unroll
    for (int o = 16; o; o >>= 1) {
        a += __shfl_down_sync(0xffffffffu, a, o);
        b += __shfl_down_sync(0xffffffffu, b, o);
    }
    if (lane == 0) { sha[w] = a; shb[w] = b; }
    __syncthreads();
    if (tid == 0) {
        float A = sha[0] + sha[1] + sha[2] + sha[3];
        float B = shb[0] + shb[1] + shb[2] + shb[3];
        float d = A - B;
        g_diff2[pair] = d * d;
    }
}

// ---------------- kernel E: final mean ----------------
__global__ void __launch_bounds__(1024) kE_final(float* __restrict__ out) {
    int tid = threadIdx.x;
    float v = g_diff2[tid] + g_diff2[tid + 1024] +
              g_diff2[tid + 2048] + g_diff2[tid + 3072];
    float total = blockReduceSum(v);
    if (tid == 0) out[0] = total * (1.0f / (float)(NBINS * NBINS));
}

// ---------------- launch ----------------
extern "C" void kernel_launch(void* const* d_in, const int* in_sizes, int n_in,
                              void* d_out, int out_size) {
    (void)in_sizes; (void)n_in; (void)out_size;
    const float* S     = (const float*)d_in[0];
    const float* T     = (const float*)d_in[1];
    const float* depth = (const float*)d_in[2];
    float* out = (float*)d_out;

    kA_bins<<<A_BLOCKS, A_THREADS>>>(depth);

    dim3 gB(C_, 2);
    kB_binsum<<<gB, B_THREADS>>>(S, T);

    dim3 gC(NBINS, 2);
    kC_protos<<<gC, C_>>>();

    kD_pairs<<<NBINS * NBINS, 128>>>();

    kE_final<<<1, 1024>>>(out);
}

// round 10
// speedup vs baseline: 1.0020x; 1.0010x over previous
#include <cuda_runtime.h>

// Problem shape (fixed by the dataset's setup_inputs): N=4, C=256, H=128, W=160
#define N_      4
#define C_      256
#define H_      128
#define W_      160
#define HW_     (H_ * W_)          // 20480
#define P_      (N_ * HW_)         // 81920 pixels
#define NBINS   64
#define NSEG    (NBINS + 1)        // 65 segments (bin 64 = invalid/overflow, dropped)
#define A_THREADS 1024
#define A_BLOCKS  (P_ / A_THREADS) // 80
#define B_THREADS 128
#define EPS_NORM  1e-12f

// ---------------- scratch (device globals; no allocation allowed) ----------------
__device__ unsigned char g_idx[P_];                 // per-pixel bin id (0..64)
__device__ int           g_pcount[A_BLOCKS * NSEG]; // per-block partial bin counts
__device__ float         g_sums[2][NBINS * C_];     // per-bin channel sums (S, T)
__device__ float         g_protos[2][NBINS * C_];   // normalized prototypes
__device__ float         g_diff2[NBINS * NBINS];    // per-pair (simS - simT)^2

// ---------------- helpers ----------------
__device__ __forceinline__ float blockReduceSum(float v) {
    __shared__ float sh[32];
    int lane = threadIdx.x & 31;
    int w    = threadIdx.x >> 5;
    #pragma unroll
    for (int o = 16; o; o >>= 1) v += __shfl_down_sync(0xffffffffu, v, o);
    __syncthreads();                 // protect sh from a previous invocation
    if (lane == 0) sh[w] = v;
    __syncthreads();
    int nw = (blockDim.x + 31) >> 5;
    float r = (threadIdx.x < nw) ? sh[threadIdx.x] : 0.0f;
    if (w == 0) {
        #pragma unroll
        for (int o = 16; o; o >>= 1) r += __shfl_down_sync(0xffffffffu, r, o);
    }
    if (threadIdx.x == 0) sh[0] = r;
    __syncthreads();
    r = sh[0];
    __syncthreads();
    return r;
}

// ---------------- kernel A: bin indices + partial counts ----------------
__global__ void __launch_bounds__(A_THREADS) kA_bins(const float* __restrict__ depth) {
    __shared__ int sc[NSEG];
    int tid = threadIdx.x;
    if (tid < NSEG) sc[tid] = 0;
    __syncthreads();

    int p = blockIdx.x * A_THREADS + tid;
    float d = depth[p];
    float f = d * 64.0f;             // (d - 0) / (1/64), exact (power of two)
    int b;
    if (f >= 0.0f && f <= 64.0f) {   // NaN fails both -> invalid
        b = (int)f;                  // truncation toward zero, matches int cast
    } else {
        b = NBINS;                   // invalid -> segment 64 (dropped)
    }
    g_idx[p] = (unsigned char)b;
    atomicAdd(&sc[b], 1);
    __syncthreads();
    if (tid < NSEG) g_pcount[blockIdx.x * NSEG + tid] = sc[tid];
}

// ---------------- kernel B: per-bin channel sums (the heavy one) ----------------
// grid (C_, 2): blockIdx.x = channel, blockIdx.y = tensor (0=S, 1=T).
// Per-thread privatized bins, bin-major layout acc[bin*128 + tid]:
// each lane always hits bank (tid & 31) -> conflict-free RMW, no atomics.
__global__ void __launch_bounds__(B_THREADS) kB_binsum(const float* __restrict__ fS,
                                                       const float* __restrict__ fT) {
    __shared__ float acc[NSEG * B_THREADS];  // 65*128*4 = 33,280 B
    const float* feats = (blockIdx.y == 0) ? fS : fT;
    const int c   = blockIdx.x;
    const int tid = threadIdx.x;

    #pragma unroll
    for (int i = tid; i < NSEG * B_THREADS; i += B_THREADS) acc[i] = 0.0f;
    __syncthreads();

    const int QUADS = HW_ / 4;  // 5120 float4 per (n, c) chunk
    for (int n = 0; n < N_; n++) {
        const float4* __restrict__ src =
            reinterpret_cast<const float4*>(feats) + (size_t)(n * C_ + c) * QUADS;
        const uchar4* __restrict__ bsrc =
            reinterpret_cast<const uchar4*>(g_idx) + (size_t)n * QUADS;

        // 5120 quads / (128 threads * 4-deep batch) = 10 iterations, exact.
        for (int q0 = tid; q0 < QUADS; q0 += B_THREADS * 4) {
            // batch loads first -> MLP 8 per warp, hides DRAM latency
            float4 v0 = src[q0];
            float4 v1 = src[q0 + B_THREADS];
            float4 v2 = src[q0 + 2 * B_THREADS];
            float4 v3 = src[q0 + 3 * B_THREADS];
            uchar4 b0 = bsrc[q0];
            uchar4 b1 = bsrc[q0 + B_THREADS];
            uchar4 b2 = bsrc[q0 + 2 * B_THREADS];
            uchar4 b3 = bsrc[q0 + 3 * B_THREADS];

            acc[b0.x * B_THREADS + tid] += v0.x;
            acc[b0.y * B_THREADS + tid] += v0.y;
            acc[b0.z * B_THREADS + tid] += v0.z;
            acc[b0.w * B_THREADS + tid] += v0.w;
            acc[b1.x * B_THREADS + tid] += v1.x;
            acc[b1.y * B_THREADS + tid] += v1.y;
            acc[b1.z * B_THREADS + tid] += v1.z;
            acc[b1.w * B_THREADS + tid] += v1.w;
            acc[b2.x * B_THREADS + tid] += v2.x;
            acc[b2.y * B_THREADS + tid] += v2.y;
            acc[b2.z * B_THREADS + tid] += v2.z;
            acc[b2.w * B_THREADS + tid] += v2.w;
            acc[b3.x * B_THREADS + tid] += v3.x;
            acc[b3.y * B_THREADS + tid] += v3.y;
            acc[b3.z * B_THREADS + tid] += v3.z;
            acc[b3.w * B_THREADS + tid] += v3.w;
        }
    }
    __syncthreads();

    // Reduce 128 partials per bin; write bins 0..63 only (bin 64 dropped).
    int warp = tid >> 5, lane = tid & 31;
    for (int b = warp; b < NBINS; b += 4) {
        const float* row = &acc[b * B_THREADS];
        float s = row[lane] + row[lane + 32] + row[lane + 64] + row[lane + 96];
        #pragma unroll
        for (int o = 16; o; o >>= 1) s += __shfl_down_sync(0xffffffffu, s, o);
        if (lane == 0) g_sums[blockIdx.y][b * C_ + c] = s;
    }
}

// ---------------- kernel C: counts reduce + mean + L2-normalize ----------------
// grid (NBINS, 2), 256 threads; thread t = channel t.
__global__ void __launch_bounds__(C_) kC_protos() {
    const int bin = blockIdx.x;
    const int ten = blockIdx.y;
    const int tid = threadIdx.x;

    // count for this bin (sum of per-block partials; exact in fp32, <= 81920)
    float cpart = 0.0f;
    for (int k = tid; k < A_BLOCKS; k += C_) cpart += (float)g_pcount[k * NSEG + bin];
    float count = blockReduceSum(cpart);

    float inv = 1.0f / fmaxf(count, 1.0f);
    float m = g_sums[ten][bin * C_ + tid] * inv;

    float ss = blockReduceSum(m * m);
    float scale = 1.0f / fmaxf(sqrtf(ss), EPS_NORM);
    g_protos[ten][bin * C_ + tid] = m * scale;
}

// ---------------- kernel D: per-pair Gram diff^2 ----------------
// grid NBINS*NBINS, 128 threads. Protos (128 KB total) are L2-hot.
__global__ void __launch_bounds__(128) kD_pairs() {
    const int pair = blockIdx.x;
    const int i = pair >> 6;
    const int j = pair & 63;
    const int tid = threadIdx.x;

    const float* pS = g_protos[0];
    const float* pT = g_protos[1];

    float a = pS[i * C_ + tid] * pS[j * C_ + tid] +
              pS[i * C_ + tid + 128] * pS[j * C_ + tid + 128];
    float b = pT[i * C_ + tid] * pT[j * C_ + tid] +
              pT[i * C_ + tid + 128] * pT[j * C_ + tid + 128];

    __shared__ float sha[4], shb[4];
    int lane = tid & 31, w = tid >> 5;
    #pragma unroll
    for (int o = 16; o; o >>= 1) {
        a += __shfl_down_sync(0xffffffffu, a, o);
        b += __shfl_down_sync(0xffffffffu, b, o);
    }
    if (lane == 0) { sha[w] = a; shb[w] = b; }
    __syncthreads();
    if (tid == 0) {
        float A = sha[0] + sha[1] + sha[2] + sha[3];
        float B = shb[0] + shb[1] + shb[2] + shb[3];
        float d = A - B;
        g_diff2[pair] = d * d;
    }
}

// ---------------- kernel E: final mean ----------------
__global__ void __launch_bounds__(1024) kE_final(float* __restrict__ out) {
    int tid = threadIdx.x;
    float v = g_diff2[tid] + g_diff2[tid + 1024] +
              g_diff2[tid + 2048] + g_diff2[tid + 3072];
    float total = blockReduceSum(v);
    if (tid == 0) out[0] = total * (1.0f / (float)(NBINS * NBINS));
}

// ---------------- launch ----------------
extern "C" void kernel_launch(void* const* d_in, const int* in_sizes, int n_in,
                              void* d_out, int out_size) {
    (void)in_sizes; (void)n_in; (void)out_size;
    const float* S     = (const float*)d_in[0];
    const float* T     = (const float*)d_in[1];
    const float* depth = (const float*)d_in[2];
    float* out = (float*)d_out;

    kA_bins<<<A_BLOCKS, A_THREADS>>>(depth);

    dim3 gB(C_, 2);
    kB_binsum<<<gB, B_THREADS>>>(S, T);

    dim3 gC(NBINS, 2);
    kC_protos<<<gC, C_>>>();

    kD_pairs<<<NBINS * NBINS, 128>>>();

    kE_final<<<1, 1024>>>(out);
}